// round 7
// baseline (speedup 1.0000x reference)
#include <cuda_runtime.h>
#include <cuda_fp16.h>
#include <cstdint>

#define N_TOK 4096
#define C_CH  256
#define C_RED 64
#define B_SZ  4

// fp16 copies of inputs
__device__ __half g_xh[B_SZ * C_CH * N_TOK];   // [b][c][n]
__device__ __half g_wh[192 * C_CH];            // [r(Q0-63,K64-127,V128-191)][c]
__device__ __half g_wph[C_CH * C_RED];         // [c][r] 128B rows
// fp16 scratch: Q (pre-scaled by 0.125*log2e), K, V all [b][token][d], 128B rows
__device__ __half g_q[B_SZ * N_TOK * C_RED];
__device__ __half g_k[B_SZ * N_TOK * C_RED];
__device__ __half g_v[B_SZ * N_TOK * C_RED];

#define SW128(off) ((off) ^ (((off) >> 3) & 0x70))
#define SW256(off) ((off) ^ (((off) >> 4) & 0x70))

__device__ __forceinline__ uint32_t smem_u32(const void* p) {
    uint32_t a;
    asm("{ .reg .u64 t; cvta.to.shared.u64 t, %1; cvt.u32.u64 %0, t; }" : "=r"(a) : "l"(p));
    return a;
}
__device__ __forceinline__ void cp16(uint32_t dst, const void* src) {
    uint64_t g;
    asm("cvta.to.global.u64 %0, %1;" : "=l"(g) : "l"(src));
    asm volatile("cp.async.cg.shared.global [%0], [%1], 16;" :: "r"(dst), "l"(g) : "memory");
}
#define CP_COMMIT() asm volatile("cp.async.commit_group;" ::: "memory")
#define CP_WAIT0()  asm volatile("cp.async.wait_group 0;" ::: "memory")

__device__ __forceinline__ void ldsm4(uint32_t (&r)[4], uint32_t addr) {
    asm volatile("ldmatrix.sync.aligned.m8n8.x4.shared.b16 {%0,%1,%2,%3}, [%4];"
        : "=r"(r[0]), "=r"(r[1]), "=r"(r[2]), "=r"(r[3]) : "r"(addr));
}
__device__ __forceinline__ void ldsm4t(uint32_t (&r)[4], uint32_t addr) {
    asm volatile("ldmatrix.sync.aligned.m8n8.x4.trans.shared.b16 {%0,%1,%2,%3}, [%4];"
        : "=r"(r[0]), "=r"(r[1]), "=r"(r[2]), "=r"(r[3]) : "r"(addr));
}
__device__ __forceinline__ void mma_f16(float* d, const uint32_t* a, uint32_t b0, uint32_t b1) {
    asm volatile(
        "mma.sync.aligned.m16n8k16.row.col.f32.f16.f16.f32 "
        "{%0,%1,%2,%3}, {%4,%5,%6,%7}, {%8,%9}, {%0,%1,%2,%3};"
        : "+f"(d[0]), "+f"(d[1]), "+f"(d[2]), "+f"(d[3])
        : "r"(a[0]), "r"(a[1]), "r"(a[2]), "r"(a[3]), "r"(b0), "r"(b1));
}
__device__ __forceinline__ uint32_t exp2_h2(uint32_t s) {
    uint32_t r;
    asm("ex2.approx.f16x2 %0, %1;" : "=r"(r) : "r"(s));
    return r;
}
__device__ __forceinline__ uint32_t packh(float lo, float hi) {
    __half2 h = __floats2half2_rn(lo, hi);
    return *(uint32_t*)&h;
}

// ---------------------------------------------------------------------------
// Convert x, Wqkv (concat), Wp to fp16.  float4 vectorized.
// ---------------------------------------------------------------------------
#define NX4 (B_SZ * C_CH * N_TOK / 4)
#define NW4 (192 * C_CH / 4)
#define NP4 (C_CH * C_RED / 4)
__global__ __launch_bounds__(256) void convert_kernel(
    const float* __restrict__ x,
    const float* __restrict__ Wq,
    const float* __restrict__ Wk,
    const float* __restrict__ Wv,
    const float* __restrict__ Wp)
{
    int stride = gridDim.x * blockDim.x;
    for (int i = blockIdx.x * blockDim.x + threadIdx.x;
         i < NX4 + NW4 + NP4; i += stride) {
        float4 v;
        __half* dst;
        int o;
        if (i < NX4) {
            v = ((const float4*)x)[i];
            dst = g_xh; o = i * 4;
        } else if (i < NX4 + NW4) {
            int e = (i - NX4) * 4;
            int r = e >> 8, c = e & 255;
            const float* W = (r < 64) ? Wq : (r < 128) ? Wk : Wv;
            v = *(const float4*)(W + (r & 63) * C_CH + c);
            dst = g_wh; o = e;
        } else {
            int e = (i - NX4 - NW4) * 4;
            v = *(const float4*)(Wp + e);
            dst = g_wph; o = e;
        }
        uint2 u;
        u.x = packh(v.x, v.y);
        u.y = packh(v.z, v.w);
        *(uint2*)(dst + o) = u;
    }
}

// ---------------------------------------------------------------------------
// Tensorized fused QKV: per CTA 128 tokens x 192 rows, K=256 in 4 chunks.
// Q rows are pre-scaled by 0.125*log2(e) so attention feeds ex2 directly.
// ---------------------------------------------------------------------------
#define QKV_SMEM 81920
__global__ __launch_bounds__(384) void qkv_tc_kernel()
{
    extern __shared__ char smem[];
    const uint32_t sb = smem_u32(smem);
    const int tid = threadIdx.x;
    const int lane = tid & 31;
    const int w = tid >> 5;
    const int n0 = blockIdx.x * 128;
    const int b  = blockIdx.y;
    const int rl = ((lane >> 3) & 1) * 8 + (lane & 7);
    const int cb = (lane >> 4) * 16;

    auto issue_chunk = [&](int ch) {
        const int c0 = ch * 64;
        const uint32_t WS = (ch & 1) * 24576;
        const uint32_t XS = 49152 + (ch & 1) * 16384;
        for (int i = tid; i < 2560; i += 384) {
            if (i < 1024) {
                int c = i >> 4, t16 = i & 15;
                cp16(sb + XS + SW256((uint32_t)c * 256 + t16 * 16),
                     g_xh + ((size_t)(b * C_CH) + c0 + c) * N_TOK + n0 + t16 * 8);
            } else {
                int g = i - 1024;
                int r = g >> 3, c16 = g & 7;
                cp16(sb + WS + SW128((uint32_t)r * 128 + c16 * 16),
                     g_wh + (size_t)r * C_CH + c0 + c16 * 8);
            }
        }
        CP_COMMIT();
    };

    issue_chunk(0);

    float acc[2][8][4] = {};
    const int mbase = (w & 3) * 32;
    const int rbase = (w >> 2) * 64;

    for (int ch = 0; ch < 4; ch++) {
        CP_WAIT0();
        __syncthreads();
        if (ch < 3) issue_chunk(ch + 1);
        const uint32_t WS = sb + (ch & 1) * 24576;
        const uint32_t XS = sb + 49152 + (ch & 1) * 16384;

        #pragma unroll
        for (int ks = 0; ks < 4; ks++) {
            uint32_t af[2][4];
            #pragma unroll
            for (int mt = 0; mt < 2; mt++) {
                uint32_t v[4];
                ldsm4t(v, XS + SW256((uint32_t)(ks * 16 + rl) * 256 + (mbase + mt * 16) * 2 + cb));
                af[mt][0] = v[0]; af[mt][1] = v[2]; af[mt][2] = v[1]; af[mt][3] = v[3];
            }
            #pragma unroll
            for (int nb2 = 0; nb2 < 4; nb2++) {
                uint32_t wf[4];
                ldsm4(wf, WS + SW128((uint32_t)(rbase + nb2 * 16 + rl) * 128 + ks * 32 + cb));
                #pragma unroll
                for (int mt = 0; mt < 2; mt++) {
                    mma_f16(acc[mt][2 * nb2],     af[mt], wf[0], wf[2]);
                    mma_f16(acc[mt][2 * nb2 + 1], af[mt], wf[1], wf[3]);
                }
            }
        }
    }

    // Q gets the softmax scale folded in (0.125 * log2(e))
    const float qs = (rbase == 0) ? 0.18033688011112042f : 1.0f;
    __half* garr = (w >> 2) == 0 ? g_q : (w >> 2) == 1 ? g_k : g_v;
    #pragma unroll
    for (int mt = 0; mt < 2; mt++)
        #pragma unroll
        for (int nt = 0; nt < 8; nt++) {
            int token = n0 + mbase + mt * 16 + (lane >> 2);
            int r = nt * 8 + (lane & 3) * 2;
            uint32_t v01 = packh(acc[mt][nt][0] * qs, acc[mt][nt][1] * qs);
            uint32_t v23 = packh(acc[mt][nt][2] * qs, acc[mt][nt][3] * qs);
            *(uint32_t*)&garr[((size_t)(b * N_TOK) + token) * C_RED + r] = v01;
            *(uint32_t*)&garr[((size_t)(b * N_TOK) + token + 8) * C_RED + r] = v23;
        }
}

// ---------------------------------------------------------------------------
// Fused HMMA flash attention + output projection + residual.  fp16 path.
// smem: Q 16K @0 (reused as f16 O tile); KV buf0 @16384; buf1 @49152;
//       Wp @81920.  Total 114688.
// ---------------------------------------------------------------------------
#define ATTN_SMEM 114688
#define WP_OFF 81920
__global__ __launch_bounds__(256, 1) void attn_mma_kernel(
    const float* __restrict__ x,
    float* __restrict__ out)
{
    extern __shared__ char smem[];
    const uint32_t sb = smem_u32(smem);
    const int tid  = threadIdx.x;
    const int lane = tid & 31;
    const int w    = tid >> 5;
    const int n0   = blockIdx.x * 128;
    const int b    = blockIdx.y;
    const int rl = ((lane >> 3) & 1) * 8 + (lane & 7);
    const int cb = (lane >> 4) * 16;

    auto issue_kv = [&](int kt) {
        const int m0 = kt * 128;
        const uint32_t base = 16384 + (kt & 1) * 32768;
        for (int i = tid; i < 2048; i += 256) {
            const __half* src = (i < 1024) ? g_k : g_v;
            uint32_t off = (i < 1024) ? base : base + 16384;
            int g = i & 1023;
            int row = g >> 3, c16 = g & 7;
            cp16(sb + off + SW128((uint32_t)row * 128 + c16 * 16),
                 src + ((size_t)(b * N_TOK) + m0 + row) * C_RED + c16 * 8);
        }
        CP_COMMIT();
    };

    // prologue: Q + Wp, then KV tile 0
    {
        for (int i = tid; i < 3072; i += 256) {
            if (i < 1024) {
                int row = i >> 3, c16 = i & 7;
                cp16(sb + SW128((uint32_t)row * 128 + c16 * 16),
                     g_q + ((size_t)(b * N_TOK) + n0 + row) * C_RED + c16 * 8);
            } else {
                int g = i - 1024;
                int row = g >> 3, c16 = g & 7;
                cp16(sb + WP_OFF + SW128((uint32_t)row * 128 + c16 * 16),
                     g_wph + (size_t)row * C_RED + c16 * 8);
            }
        }
        CP_COMMIT();
        issue_kv(0);
    }

    uint32_t qf[4][4];
    float oacc[8][4] = {};
    float l0 = 0.0f, l1 = 0.0f;

    for (int kt = 0; kt < N_TOK / 128; kt++) {
        CP_WAIT0();
        __syncthreads();
        if (kt < N_TOK / 128 - 1) issue_kv(kt + 1);
        if (kt == 0) {
            uint32_t rowoff = (uint32_t)(w * 16 + rl) * 128 + cb;
            #pragma unroll
            for (int ks = 0; ks < 4; ks++)
                ldsm4(qf[ks], sb + SW128(rowoff + ks * 32));
        }
        const uint32_t SK = sb + 16384 + (kt & 1) * 32768;
        const uint32_t SV = SK + 16384;

        // ---- S = Q K^T (Q pre-scaled so S is the ex2 argument) ----
        float sacc[16][4];
        #pragma unroll
        for (int t = 0; t < 16; t++)
            #pragma unroll
            for (int c = 0; c < 4; c++) sacc[t][c] = 0.0f;

        #pragma unroll
        for (int nb = 0; nb < 8; nb++) {
            uint32_t tokoff = (uint32_t)(nb * 16 + rl) * 128 + cb;
            #pragma unroll
            for (int ks = 0; ks < 4; ks++) {
                uint32_t kf[4];
                ldsm4(kf, SK + SW128(tokoff + ks * 32));
                mma_f16(sacc[2 * nb],     qf[ks], kf[0], kf[2]);
                mma_f16(sacc[2 * nb + 1], qf[ks], kf[1], kf[3]);
            }
        }

        // ---- fused softmax (packed f16x2 ex2) + PV ----
        __half2 hl0 = __float2half2_rn(0.0f);
        __half2 hl1 = __float2half2_rn(0.0f);
        #pragma unroll
        for (int j = 0; j < 8; j++) {
            uint32_t pf[4];
            pf[0] = exp2_h2(packh(sacc[2 * j][0],     sacc[2 * j][1]));
            pf[1] = exp2_h2(packh(sacc[2 * j][2],     sacc[2 * j][3]));
            pf[2] = exp2_h2(packh(sacc[2 * j + 1][0], sacc[2 * j + 1][1]));
            pf[3] = exp2_h2(packh(sacc[2 * j + 1][2], sacc[2 * j + 1][3]));
            hl0 = __hadd2(hl0, __hadd2(*(__half2*)&pf[0], *(__half2*)&pf[2]));
            hl1 = __hadd2(hl1, __hadd2(*(__half2*)&pf[1], *(__half2*)&pf[3]));

            uint32_t tokoff = (uint32_t)(j * 16 + rl) * 128 + cb;
            #pragma unroll
            for (int db = 0; db < 4; db++) {
                uint32_t vf[4];
                ldsm4t(vf, SV + SW128(tokoff + db * 32));
                mma_f16(oacc[2 * db],     pf, vf[0], vf[1]);
                mma_f16(oacc[2 * db + 1], pf, vf[2], vf[3]);
            }
        }
        float2 f0 = __half22float2(hl0);
        float2 f1 = __half22float2(hl1);
        l0 += f0.x + f0.y;
        l1 += f1.x + f1.y;
    }

    // ---- normalize O, stage as f16 into smem (reuse Q region) ----
    l0 += __shfl_xor_sync(0xffffffffu, l0, 1);
    l0 += __shfl_xor_sync(0xffffffffu, l0, 2);
    l1 += __shfl_xor_sync(0xffffffffu, l1, 1);
    l1 += __shfl_xor_sync(0xffffffffu, l1, 2);
    float i0 = 1.0f / l0, i1 = 1.0f / l1;

    {
        int lr = w * 16 + (lane >> 2);
        #pragma unroll
        for (int t = 0; t < 8; t++) {
            uint32_t cbyte = (uint32_t)(t * 8 + (lane & 3) * 2) * 2;
            *(uint32_t*)(smem + SW128((uint32_t)lr * 128 + cbyte)) =
                packh(oacc[t][0] * i0, oacc[t][1] * i0);
            *(uint32_t*)(smem + SW128((uint32_t)(lr + 8) * 128 + cbyte)) =
                packh(oacc[t][2] * i1, oacc[t][3] * i1);
        }
    }
    __syncthreads();

    // ---- projection: out[c][tok] = Wp[c][r] * O[tok][r] + x ----
    const int cg = w & 3, tg = w >> 2;
    float pacc[4][8][4] = {};
    #pragma unroll
    for (int ks = 0; ks < 4; ks++) {
        uint32_t awf[4][4];
        #pragma unroll
        for (int mt = 0; mt < 4; mt++)
            ldsm4(awf[mt], sb + WP_OFF +
                  SW128((uint32_t)(cg * 64 + mt * 16 + rl) * 128 + ks * 32 + cb));
        #pragma unroll
        for (int nb = 0; nb < 4; nb++) {
            uint32_t of[4];
            ldsm4(of, sb + SW128((uint32_t)(tg * 64 + nb * 16 + rl) * 128 + ks * 32 + cb));
            #pragma unroll
            for (int mt = 0; mt < 4; mt++) {
                mma_f16(pacc[mt][2 * nb],     awf[mt], of[0], of[2]);
                mma_f16(pacc[mt][2 * nb + 1], awf[mt], of[1], of[3]);
            }
        }
    }

    // ---- epilogue: residual add + store ----
    #pragma unroll
    for (int mt = 0; mt < 4; mt++) {
        int c = cg * 64 + mt * 16 + (lane >> 2);
        #pragma unroll
        for (int nt = 0; nt < 8; nt++) {
            int tok = n0 + tg * 64 + nt * 8 + (lane & 3) * 2;
            size_t gi = ((size_t)(b * C_CH + c)) * N_TOK + tok;
            float2 x0 = *(const float2*)(x + gi);
            float2 x1 = *(const float2*)(x + gi + 8 * N_TOK);
            *(float2*)(out + gi) =
                make_float2(pacc[mt][nt][0] + x0.x, pacc[mt][nt][1] + x0.y);
            *(float2*)(out + gi + 8 * N_TOK) =
                make_float2(pacc[mt][nt][2] + x1.x, pacc[mt][nt][3] + x1.y);
        }
    }
}

extern "C" void kernel_launch(void* const* d_in, const int* in_sizes, int n_in,
                              void* d_out, int out_size)
{
    const float* x  = (const float*)d_in[0];
    const float* Wq = (const float*)d_in[1];
    const float* Wk = (const float*)d_in[2];
    const float* Wv = (const float*)d_in[3];
    const float* Wp = (const float*)d_in[4];
    float* out = (float*)d_out;

    cudaFuncSetAttribute(qkv_tc_kernel,   cudaFuncAttributeMaxDynamicSharedMemorySize, QKV_SMEM);
    cudaFuncSetAttribute(attn_mma_kernel, cudaFuncAttributeMaxDynamicSharedMemorySize, ATTN_SMEM);

    convert_kernel<<<2048, 256>>>(x, Wq, Wk, Wv, Wp);
    qkv_tc_kernel <<<dim3(N_TOK / 128, B_SZ), 384, QKV_SMEM>>>();
    attn_mma_kernel<<<dim3(N_TOK / 128, B_SZ), 256, ATTN_SMEM>>>(x, out);
}

// round 9
// speedup vs baseline: 1.0283x; 1.0283x over previous
#include <cuda_runtime.h>
#include <cuda_fp16.h>
#include <cstdint>

#define N_TOK 4096
#define C_CH  256
#define C_RED 64
#define B_SZ  4

// fp16 copies of inputs
__device__ __half g_xh[B_SZ * C_CH * N_TOK];   // [b][c][n]
__device__ __half g_wh[192 * C_CH];            // [r(Q0-63,K64-127,V128-191)][c]
__device__ __half g_wph[C_CH * C_RED];         // [c][r] 128B rows
// fp16 scratch: Q (pre-scaled by 0.125*log2e), K, V all [b][token][d], 128B rows
__device__ __half g_q[B_SZ * N_TOK * C_RED];
__device__ __half g_k[B_SZ * N_TOK * C_RED];
__device__ __half g_v[B_SZ * N_TOK * C_RED];

#define SW128(off) ((off) ^ (((off) >> 3) & 0x70))
#define SW256(off) ((off) ^ (((off) >> 4) & 0x70))

__device__ __forceinline__ uint32_t smem_u32(const void* p) {
    uint32_t a;
    asm("{ .reg .u64 t; cvta.to.shared.u64 t, %1; cvt.u32.u64 %0, t; }" : "=r"(a) : "l"(p));
    return a;
}
__device__ __forceinline__ void cp16(uint32_t dst, const void* src) {
    uint64_t g;
    asm("cvta.to.global.u64 %0, %1;" : "=l"(g) : "l"(src));
    asm volatile("cp.async.cg.shared.global [%0], [%1], 16;" :: "r"(dst), "l"(g) : "memory");
}
#define CP_COMMIT() asm volatile("cp.async.commit_group;" ::: "memory")
#define CP_WAIT0()  asm volatile("cp.async.wait_group 0;" ::: "memory")
#define CP_WAIT1()  asm volatile("cp.async.wait_group 1;" ::: "memory")

__device__ __forceinline__ void ldsm4(uint32_t (&r)[4], uint32_t addr) {
    asm volatile("ldmatrix.sync.aligned.m8n8.x4.shared.b16 {%0,%1,%2,%3}, [%4];"
        : "=r"(r[0]), "=r"(r[1]), "=r"(r[2]), "=r"(r[3]) : "r"(addr));
}
__device__ __forceinline__ void ldsm4t(uint32_t (&r)[4], uint32_t addr) {
    asm volatile("ldmatrix.sync.aligned.m8n8.x4.trans.shared.b16 {%0,%1,%2,%3}, [%4];"
        : "=r"(r[0]), "=r"(r[1]), "=r"(r[2]), "=r"(r[3]) : "r"(addr));
}
__device__ __forceinline__ void mma_f16(float* d, const uint32_t* a, uint32_t b0, uint32_t b1) {
    asm volatile(
        "mma.sync.aligned.m16n8k16.row.col.f32.f16.f16.f32 "
        "{%0,%1,%2,%3}, {%4,%5,%6,%7}, {%8,%9}, {%0,%1,%2,%3};"
        : "+f"(d[0]), "+f"(d[1]), "+f"(d[2]), "+f"(d[3])
        : "r"(a[0]), "r"(a[1]), "r"(a[2]), "r"(a[3]), "r"(b0), "r"(b1));
}
__device__ __forceinline__ uint32_t exp2_h2(uint32_t s) {
    uint32_t r;
    asm("ex2.approx.f16x2 %0, %1;" : "=r"(r) : "r"(s));
    return r;
}
__device__ __forceinline__ uint32_t packh(float lo, float hi) {
    __half2 h = __floats2half2_rn(lo, hi);
    return *(uint32_t*)&h;
}

// ---------------------------------------------------------------------------
// Convert x, Wqkv (concat), Wp to fp16.  float4 + MLP=4.
// ---------------------------------------------------------------------------
#define NX4 (B_SZ * C_CH * N_TOK / 4)
#define NW4 (192 * C_CH / 4)
#define NP4 (C_CH * C_RED / 4)
#define TOTAL4 (NX4 + NW4 + NP4)
__global__ __launch_bounds__(256) void convert_kernel(
    const float* __restrict__ x,
    const float* __restrict__ Wq,
    const float* __restrict__ Wk,
    const float* __restrict__ Wv,
    const float* __restrict__ Wp)
{
    const int T = gridDim.x * blockDim.x;
    int i = blockIdx.x * blockDim.x + threadIdx.x;
    #pragma unroll
    for (int u = 0; u < 4; u++, i += T) {
        if (i >= TOTAL4) break;
        float4 v;
        __half* dst;
        int o;
        if (i < NX4) {
            v = ((const float4*)x)[i];
            dst = g_xh; o = i * 4;
        } else if (i < NX4 + NW4) {
            int e = (i - NX4) * 4;
            int r = e >> 8, c = e & 255;
            const float* W = (r < 64) ? Wq : (r < 128) ? Wk : Wv;
            v = *(const float4*)(W + (r & 63) * C_CH + c);
            dst = g_wh; o = e;
        } else {
            int e = (i - NX4 - NW4) * 4;
            v = *(const float4*)(Wp + e);
            dst = g_wph; o = e;
        }
        uint2 u2;
        u2.x = packh(v.x, v.y);
        u2.y = packh(v.z, v.w);
        *(uint2*)(dst + o) = u2;
    }
}

// ---------------------------------------------------------------------------
// Tensorized fused QKV: per CTA 128 tokens x 192 rows, K=256 in 4 chunks,
// 3-stage cp.async pipeline (wait_group 1).
// smem: W [192][64]x3 @0/24576/49152; X [64][128]x3 @73728/90112/106496.
// ---------------------------------------------------------------------------
#define QKV_SMEM 122880
__global__ __launch_bounds__(384) void qkv_tc_kernel()
{
    extern __shared__ char smem[];
    const uint32_t sb = smem_u32(smem);
    const int tid = threadIdx.x;
    const int lane = tid & 31;
    const int w = tid >> 5;
    const int n0 = blockIdx.x * 128;
    const int b  = blockIdx.y;
    const int rl = ((lane >> 3) & 1) * 8 + (lane & 7);
    const int cb = (lane >> 4) * 16;

    auto issue_chunk = [&](int ch) {
        const int c0 = ch * 64;
        const int s = ch % 3;
        const uint32_t WS = s * 24576u;
        const uint32_t XS = 73728u + s * 16384u;
        for (int i = tid; i < 2560; i += 384) {
            if (i < 1024) {
                int c = i >> 4, t16 = i & 15;
                cp16(sb + XS + SW256((uint32_t)c * 256 + t16 * 16),
                     g_xh + ((size_t)(b * C_CH) + c0 + c) * N_TOK + n0 + t16 * 8);
            } else {
                int g = i - 1024;
                int r = g >> 3, c16 = g & 7;
                cp16(sb + WS + SW128((uint32_t)r * 128 + c16 * 16),
                     g_wh + (size_t)r * C_CH + c0 + c16 * 8);
            }
        }
        CP_COMMIT();
    };

    issue_chunk(0);
    issue_chunk(1);

    float acc[2][8][4] = {};
    const int mbase = (w & 3) * 32;
    const int rbase = (w >> 2) * 64;

    for (int ch = 0; ch < 4; ch++) {
        if (ch < 3) CP_WAIT1(); else CP_WAIT0();
        __syncthreads();
        if (ch + 2 <= 3) issue_chunk(ch + 2);
        const int s = ch % 3;
        const uint32_t WS = sb + s * 24576u;
        const uint32_t XS = sb + 73728u + s * 16384u;

        #pragma unroll
        for (int ks = 0; ks < 4; ks++) {
            uint32_t af[2][4];
            #pragma unroll
            for (int mt = 0; mt < 2; mt++) {
                uint32_t v[4];
                ldsm4t(v, XS + SW256((uint32_t)(ks * 16 + rl) * 256 + (mbase + mt * 16) * 2 + cb));
                af[mt][0] = v[0]; af[mt][1] = v[2]; af[mt][2] = v[1]; af[mt][3] = v[3];
            }
            #pragma unroll
            for (int nb2 = 0; nb2 < 4; nb2++) {
                uint32_t wf[4];
                ldsm4(wf, WS + SW128((uint32_t)(rbase + nb2 * 16 + rl) * 128 + ks * 32 + cb));
                #pragma unroll
                for (int mt = 0; mt < 2; mt++) {
                    mma_f16(acc[mt][2 * nb2],     af[mt], wf[0], wf[2]);
                    mma_f16(acc[mt][2 * nb2 + 1], af[mt], wf[1], wf[3]);
                }
            }
        }
    }

    // Q gets the softmax scale folded in (0.125 * log2(e))
    const float qs = (rbase == 0) ? 0.18033688011112042f : 1.0f;
    __half* garr = (w >> 2) == 0 ? g_q : (w >> 2) == 1 ? g_k : g_v;
    #pragma unroll
    for (int mt = 0; mt < 2; mt++)
        #pragma unroll
        for (int nt = 0; nt < 8; nt++) {
            int token = n0 + mbase + mt * 16 + (lane >> 2);
            int r = nt * 8 + (lane & 3) * 2;
            uint32_t v01 = packh(acc[mt][nt][0] * qs, acc[mt][nt][1] * qs);
            uint32_t v23 = packh(acc[mt][nt][2] * qs, acc[mt][nt][3] * qs);
            *(uint32_t*)&garr[((size_t)(b * N_TOK) + token) * C_RED + r] = v01;
            *(uint32_t*)&garr[((size_t)(b * N_TOK) + token + 8) * C_RED + r] = v23;
        }
}

// ---------------------------------------------------------------------------
// Fused HMMA flash attention + output projection + residual.  fp16 path.
// 3-stage KV pipeline (wait_group 1).
// smem: Q 16K @0 (reused as f16 O tile); KV bufs @16384/49152/81920 (32K each);
//       Wp @114688.  Total 147456.
// ---------------------------------------------------------------------------
#define ATTN_SMEM 147456
#define WP_OFF 114688
#define NKT (N_TOK / 128)
__global__ __launch_bounds__(256, 1) void attn_mma_kernel(
    const float* __restrict__ x,
    float* __restrict__ out)
{
    extern __shared__ char smem[];
    const uint32_t sb = smem_u32(smem);
    const int tid  = threadIdx.x;
    const int lane = tid & 31;
    const int w    = tid >> 5;
    const int n0   = blockIdx.x * 128;
    const int b    = blockIdx.y;
    const int rl = ((lane >> 3) & 1) * 8 + (lane & 7);
    const int cb = (lane >> 4) * 16;

    auto issue_kv = [&](int kt) {
        const int m0 = kt * 128;
        const uint32_t base = 16384u + (uint32_t)(kt % 3) * 32768u;
        for (int i = tid; i < 2048; i += 256) {
            const __half* src = (i < 1024) ? g_k : g_v;
            uint32_t off = (i < 1024) ? base : base + 16384;
            int g = i & 1023;
            int row = g >> 3, c16 = g & 7;
            cp16(sb + off + SW128((uint32_t)row * 128 + c16 * 16),
                 src + ((size_t)(b * N_TOK) + m0 + row) * C_RED + c16 * 8);
        }
        CP_COMMIT();
    };

    // prologue: Q + Wp (group 0), then KV tiles 0 and 1 (groups 1, 2)
    {
        for (int i = tid; i < 3072; i += 256) {
            if (i < 1024) {
                int row = i >> 3, c16 = i & 7;
                cp16(sb + SW128((uint32_t)row * 128 + c16 * 16),
                     g_q + ((size_t)(b * N_TOK) + n0 + row) * C_RED + c16 * 8);
            } else {
                int g = i - 1024;
                int row = g >> 3, c16 = g & 7;
                cp16(sb + WP_OFF + SW128((uint32_t)row * 128 + c16 * 16),
                     g_wph + (size_t)row * C_RED + c16 * 8);
            }
        }
        CP_COMMIT();
        issue_kv(0);
        issue_kv(1);
    }

    uint32_t qf[4][4];
    float oacc[8][4] = {};
    float l0 = 0.0f, l1 = 0.0f;

    for (int kt = 0; kt < NKT; kt++) {
        if (kt < NKT - 1) CP_WAIT1(); else CP_WAIT0();
        __syncthreads();
        if (kt + 2 < NKT) issue_kv(kt + 2);
        if (kt == 0) {
            uint32_t rowoff = (uint32_t)(w * 16 + rl) * 128 + cb;
            #pragma unroll
            for (int ks = 0; ks < 4; ks++)
                ldsm4(qf[ks], sb + SW128(rowoff + ks * 32));
        }
        const uint32_t SK = sb + 16384u + (uint32_t)(kt % 3) * 32768u;
        const uint32_t SV = SK + 16384;

        // ---- S = Q K^T (Q pre-scaled so S is the ex2 argument) ----
        float sacc[16][4];
        #pragma unroll
        for (int t = 0; t < 16; t++)
            #pragma unroll
            for (int c = 0; c < 4; c++) sacc[t][c] = 0.0f;

        #pragma unroll
        for (int nb = 0; nb < 8; nb++) {
            uint32_t tokoff = (uint32_t)(nb * 16 + rl) * 128 + cb;
            #pragma unroll
            for (int ks = 0; ks < 4; ks++) {
                uint32_t kf[4];
                ldsm4(kf, SK + SW128(tokoff + ks * 32));
                mma_f16(sacc[2 * nb],     qf[ks], kf[0], kf[2]);
                mma_f16(sacc[2 * nb + 1], qf[ks], kf[1], kf[3]);
            }
        }

        // ---- fused softmax (packed f16x2 ex2) + PV ----
        __half2 hl0 = __float2half2_rn(0.0f);
        __half2 hl1 = __float2half2_rn(0.0f);
        #pragma unroll
        for (int j = 0; j < 8; j++) {
            uint32_t pf[4];
            pf[0] = exp2_h2(packh(sacc[2 * j][0],     sacc[2 * j][1]));
            pf[1] = exp2_h2(packh(sacc[2 * j][2],     sacc[2 * j][3]));
            pf[2] = exp2_h2(packh(sacc[2 * j + 1][0], sacc[2 * j + 1][1]));
            pf[3] = exp2_h2(packh(sacc[2 * j + 1][2], sacc[2 * j + 1][3]));
            hl0 = __hadd2(hl0, __hadd2(*(__half2*)&pf[0], *(__half2*)&pf[2]));
            hl1 = __hadd2(hl1, __hadd2(*(__half2*)&pf[1], *(__half2*)&pf[3]));

            uint32_t tokoff = (uint32_t)(j * 16 + rl) * 128 + cb;
            #pragma unroll
            for (int db = 0; db < 4; db++) {
                uint32_t vf[4];
                ldsm4t(vf, SV + SW128(tokoff + db * 32));
                mma_f16(oacc[2 * db],     pf, vf[0], vf[1]);
                mma_f16(oacc[2 * db + 1], pf, vf[2], vf[3]);
            }
        }
        float2 f0 = __half22float2(hl0);
        float2 f1 = __half22float2(hl1);
        l0 += f0.x + f0.y;
        l1 += f1.x + f1.y;
    }

    // ---- normalize O, stage as f16 into smem (reuse Q region) ----
    l0 += __shfl_xor_sync(0xffffffffu, l0, 1);
    l0 += __shfl_xor_sync(0xffffffffu, l0, 2);
    l1 += __shfl_xor_sync(0xffffffffu, l1, 1);
    l1 += __shfl_xor_sync(0xffffffffu, l1, 2);
    float i0 = 1.0f / l0, i1 = 1.0f / l1;

    {
        int lr = w * 16 + (lane >> 2);
        #pragma unroll
        for (int t = 0; t < 8; t++) {
            uint32_t cbyte = (uint32_t)(t * 8 + (lane & 3) * 2) * 2;
            *(uint32_t*)(smem + SW128((uint32_t)lr * 128 + cbyte)) =
                packh(oacc[t][0] * i0, oacc[t][1] * i0);
            *(uint32_t*)(smem + SW128((uint32_t)(lr + 8) * 128 + cbyte)) =
                packh(oacc[t][2] * i1, oacc[t][3] * i1);
        }
    }
    __syncthreads();

    // ---- projection: out[c][tok] = Wp[c][r] * O[tok][r] + x ----
    const int cg = w & 3, tg = w >> 2;
    float pacc[4][8][4] = {};
    #pragma unroll
    for (int ks = 0; ks < 4; ks++) {
        uint32_t awf[4][4];
        #pragma unroll
        for (int mt = 0; mt < 4; mt++)
            ldsm4(awf[mt], sb + WP_OFF +
                  SW128((uint32_t)(cg * 64 + mt * 16 + rl) * 128 + ks * 32 + cb));
        #pragma unroll
        for (int nb = 0; nb < 4; nb++) {
            uint32_t of[4];
            ldsm4(of, sb + SW128((uint32_t)(tg * 64 + nb * 16 + rl) * 128 + ks * 32 + cb));
            #pragma unroll
            for (int mt = 0; mt < 4; mt++) {
                mma_f16(pacc[mt][2 * nb],     awf[mt], of[0], of[2]);
                mma_f16(pacc[mt][2 * nb + 1], awf[mt], of[1], of[3]);
            }
        }
    }

    // ---- epilogue: residual add + store ----
    #pragma unroll
    for (int mt = 0; mt < 4; mt++) {
        int c = cg * 64 + mt * 16 + (lane >> 2);
        #pragma unroll
        for (int nt = 0; nt < 8; nt++) {
            int tok = n0 + tg * 64 + nt * 8 + (lane & 3) * 2;
            size_t gi = ((size_t)(b * C_CH + c)) * N_TOK + tok;
            float2 x0 = *(const float2*)(x + gi);
            float2 x1 = *(const float2*)(x + gi + 8 * N_TOK);
            *(float2*)(out + gi) =
                make_float2(pacc[mt][nt][0] + x0.x, pacc[mt][nt][1] + x0.y);
            *(float2*)(out + gi + 8 * N_TOK) =
                make_float2(pacc[mt][nt][2] + x1.x, pacc[mt][nt][3] + x1.y);
        }
    }
}

extern "C" void kernel_launch(void* const* d_in, const int* in_sizes, int n_in,
                              void* d_out, int out_size)
{
    const float* x  = (const float*)d_in[0];
    const float* Wq = (const float*)d_in[1];
    const float* Wk = (const float*)d_in[2];
    const float* Wv = (const float*)d_in[3];
    const float* Wp = (const float*)d_in[4];
    float* out = (float*)d_out;

    cudaFuncSetAttribute(qkv_tc_kernel,   cudaFuncAttributeMaxDynamicSharedMemorySize, QKV_SMEM);
    cudaFuncSetAttribute(attn_mma_kernel, cudaFuncAttributeMaxDynamicSharedMemorySize, ATTN_SMEM);

    convert_kernel<<<1040, 256>>>(x, Wq, Wk, Wv, Wp);
    qkv_tc_kernel <<<dim3(N_TOK / 128, B_SZ), 384, QKV_SMEM>>>();
    attn_mma_kernel<<<dim3(N_TOK / 128, B_SZ), 256, ATTN_SMEM>>>(x, out);
}